// round 4
// baseline (speedup 1.0000x reference)
#include <cuda_runtime.h>
#include <cuda_bf16.h>
#include <math.h>

// Problem constants
#define Bn 4
#define Sn 4096
#define Hn 2048
#define En 16
#define EDn 512
#define ROWS_PER_BLOCK 32
#define CHUNKS 128            // chunks per batch
#define NPART (Bn * CHUNKS)   // 512 partial rows

// Scratch (allocation-free: __device__ globals)
__device__ float g_partials[NPART][Hn];   // 4 MB
__device__ float g_query[Bn][Hn];
__device__ float g_features[En][Hn];
__device__ float g_q[Bn][Hn];
__device__ float g_k[En][Hn];

// ---------------------------------------------------------------------------
// Kernel 1: fused LayerNorm + partial mean over S.
// Each block: one batch b, 32 consecutive rows of S. Accumulates
// sum_s (x - mu_s) * rsqrt(var_s + eps) per h into a partial row.
// gamma/beta applied later (they factor out of the mean over S).
// ---------------------------------------------------------------------------
__global__ __launch_bounds__(256) void ln_mean_kernel(const float* __restrict__ hidden) {
    const int bid = blockIdx.x;
    const int b = bid / CHUNKS;
    const int chunk = bid % CHUNKS;
    const int t = threadIdx.x;
    const int lane = t & 31;
    const int wid = t >> 5;

    const float* base = hidden + ((size_t)b * Sn + (size_t)chunk * ROWS_PER_BLOCK) * Hn;

    float4 acc0 = make_float4(0.f, 0.f, 0.f, 0.f);
    float4 acc1 = make_float4(0.f, 0.f, 0.f, 0.f);

    __shared__ float s_red[8][4];
    __shared__ float s_fin[4];

    for (int r = 0; r < ROWS_PER_BLOCK; r += 2) {
        const float4* row0 = (const float4*)(base + (size_t)r * Hn);
        const float4* row1 = (const float4*)(base + (size_t)(r + 1) * Hn);
        float4 a0 = row0[t];
        float4 a1 = row0[t + 256];
        float4 b0 = row1[t];
        float4 b1 = row1[t + 256];

        float s0 = a0.x + a0.y + a0.z + a0.w + a1.x + a1.y + a1.z + a1.w;
        float q0 = a0.x * a0.x + a0.y * a0.y + a0.z * a0.z + a0.w * a0.w
                 + a1.x * a1.x + a1.y * a1.y + a1.z * a1.z + a1.w * a1.w;
        float s1 = b0.x + b0.y + b0.z + b0.w + b1.x + b1.y + b1.z + b1.w;
        float q1 = b0.x * b0.x + b0.y * b0.y + b0.z * b0.z + b0.w * b0.w
                 + b1.x * b1.x + b1.y * b1.y + b1.z * b1.z + b1.w * b1.w;

        #pragma unroll
        for (int off = 16; off; off >>= 1) {
            s0 += __shfl_down_sync(0xFFFFFFFFu, s0, off);
            q0 += __shfl_down_sync(0xFFFFFFFFu, q0, off);
            s1 += __shfl_down_sync(0xFFFFFFFFu, s1, off);
            q1 += __shfl_down_sync(0xFFFFFFFFu, q1, off);
        }
        if (lane == 0) {
            s_red[wid][0] = s0; s_red[wid][1] = q0;
            s_red[wid][2] = s1; s_red[wid][3] = q1;
        }
        __syncthreads();
        if (wid == 0) {
            float v0 = (lane < 8) ? s_red[lane][0] : 0.f;
            float v1 = (lane < 8) ? s_red[lane][1] : 0.f;
            float v2 = (lane < 8) ? s_red[lane][2] : 0.f;
            float v3 = (lane < 8) ? s_red[lane][3] : 0.f;
            #pragma unroll
            for (int off = 4; off; off >>= 1) {
                v0 += __shfl_down_sync(0xFFFFFFFFu, v0, off);
                v1 += __shfl_down_sync(0xFFFFFFFFu, v1, off);
                v2 += __shfl_down_sync(0xFFFFFFFFu, v2, off);
                v3 += __shfl_down_sync(0xFFFFFFFFu, v3, off);
            }
            if (lane == 0) {
                s_fin[0] = v0; s_fin[1] = v1; s_fin[2] = v2; s_fin[3] = v3;
            }
        }
        __syncthreads();
        const float inv = 1.0f / (float)Hn;
        float mu0 = s_fin[0] * inv;
        float rs0 = rsqrtf(s_fin[1] * inv - mu0 * mu0 + 1e-5f);
        float mu1 = s_fin[2] * inv;
        float rs1 = rsqrtf(s_fin[3] * inv - mu1 * mu1 + 1e-5f);

        acc0.x += (a0.x - mu0) * rs0 + (b0.x - mu1) * rs1;
        acc0.y += (a0.y - mu0) * rs0 + (b0.y - mu1) * rs1;
        acc0.z += (a0.z - mu0) * rs0 + (b0.z - mu1) * rs1;
        acc0.w += (a0.w - mu0) * rs0 + (b0.w - mu1) * rs1;
        acc1.x += (a1.x - mu0) * rs0 + (b1.x - mu1) * rs1;
        acc1.y += (a1.y - mu0) * rs0 + (b1.y - mu1) * rs1;
        acc1.z += (a1.z - mu0) * rs0 + (b1.z - mu1) * rs1;
        acc1.w += (a1.w - mu0) * rs0 + (b1.w - mu1) * rs1;
    }

    float4* p = (float4*)(&g_partials[bid][0]);
    p[t] = acc0;
    p[t + 256] = acc1;
}

// ---------------------------------------------------------------------------
// Kernel 2: reduce partials -> query_input; build features = lemb + cemb.
// ---------------------------------------------------------------------------
__global__ __launch_bounds__(256) void prep_kernel(const float* __restrict__ lemb,
                                                   const float* __restrict__ cemb,
                                                   const float* __restrict__ gamma,
                                                   const float* __restrict__ beta,
                                                   const int* __restrict__ curp) {
    int idx = blockIdx.x * blockDim.x + threadIdx.x;
    int cur = *curp;
    if (idx < Bn * Hn) {
        int b = idx / Hn, h = idx % Hn;
        float s = 0.f;
        #pragma unroll 4
        for (int p = 0; p < CHUNKS; p++) s += g_partials[b * CHUNKS + p][h];
        float hm = s * (1.0f / (float)Sn) * gamma[h] + beta[h];
        g_query[b][h] = lemb[cur * Hn + h] + hm;
    } else {
        int idx2 = idx - Bn * Hn;
        if (idx2 < En * Hn) {
            (&g_features[0][0])[idx2] = lemb[idx2] + cemb[idx2];
        }
    }
}

// ---------------------------------------------------------------------------
// Kernel 3: skinny GEMM  out[N][H] = L[N][H] @ W^T + bias.
// Warp computes 2 output columns h; lanes split the K dimension (float4).
// ---------------------------------------------------------------------------
template <int N>
__global__ __launch_bounds__(256) void qk_kernel(const float* __restrict__ L,
                                                 const float* __restrict__ W,
                                                 const float* __restrict__ bias,
                                                 float* __restrict__ out) {
    const int t = threadIdx.x;
    const int lane = t & 31;
    const int w = t >> 5;
    const int h0 = blockIdx.x * 16 + w * 2;

    const float4* W4 = (const float4*)W;
    const float4* L4 = (const float4*)L;

    float acc0[N], acc1[N];
    #pragma unroll
    for (int e = 0; e < N; e++) { acc0[e] = 0.f; acc1[e] = 0.f; }

    for (int j = 0; j < 16; j++) {
        int c4 = lane + 32 * j;  // float4 index within a 2048-float row
        float4 w0 = W4[(size_t)h0 * 512 + c4];
        float4 w1 = W4[(size_t)(h0 + 1) * 512 + c4];
        #pragma unroll
        for (int e = 0; e < N; e++) {
            float4 l = L4[e * 512 + c4];
            acc0[e] += w0.x * l.x + w0.y * l.y + w0.z * l.z + w0.w * l.w;
            acc1[e] += w1.x * l.x + w1.y * l.y + w1.z * l.z + w1.w * l.w;
        }
    }

    #pragma unroll
    for (int e = 0; e < N; e++) {
        #pragma unroll
        for (int off = 16; off; off >>= 1) {
            acc0[e] += __shfl_down_sync(0xFFFFFFFFu, acc0[e], off);
            acc1[e] += __shfl_down_sync(0xFFFFFFFFu, acc1[e], off);
        }
    }
    if (lane == 0) {
        float b0 = bias[h0], b1 = bias[h0 + 1];
        #pragma unroll
        for (int e = 0; e < N; e++) {
            out[e * Hn + h0]     = acc0[e] + b0;
            out[e * Hn + h0 + 1] = acc1[e] + b1;
        }
    }
}

// ---------------------------------------------------------------------------
// Kernel 4: scores, biases, softmax, KL loss, argmax. Single block.
// ---------------------------------------------------------------------------
__global__ __launch_bounds__(512) void final_kernel(const float* __restrict__ spatial,
                                                    const float* __restrict__ edge,
                                                    const int* __restrict__ curp,
                                                    const int* __restrict__ mask,
                                                    float* __restrict__ out,
                                                    int out_size) {
    __shared__ float s_u[EDn];
    __shared__ float s_eb[En];
    __shared__ float s_att[Bn * En];
    __shared__ float s_probs[Bn][En];

    const int t = threadIdx.x;
    const int lane = t & 31;
    const int w = t >> 5;
    const int cur = *curp;

    // 1. u[d] = sum_i coef_i * edge[i][d]
    if (t < EDn) {
        float u = 0.f;
        #pragma unroll
        for (int i = 0; i < En; i++) {
            int d = abs(i - cur);
            float coef = (mask[i] != 0 && i != cur) ? 1.0f / (float)max(d, 1) : 0.0f;
            u += coef * edge[i * EDn + t];
        }
        s_u[t] = u;
    }
    __syncthreads();

    // 2. edge_bias[j] = dot(u, edge[j]) : one warp per j
    {
        float s = 0.f;
        const float* ej = edge + w * EDn;
        for (int d = lane; d < EDn; d += 32) s += s_u[d] * ej[d];
        #pragma unroll
        for (int off = 16; off; off >>= 1) s += __shfl_down_sync(0xFFFFFFFFu, s, off);
        if (lane == 0) s_eb[w] = s;
    }

    // 3. attention[b][e] = dot(q[b], k[e]); warp w handles 4 pairs
    for (int r = 0; r < 4; r++) {
        int p = w * 4 + r;
        int b = p >> 4;
        int e = p & 15;
        const float4* q4 = (const float4*)(&g_q[b][0]);
        const float4* k4 = (const float4*)(&g_k[e][0]);
        float s = 0.f;
        #pragma unroll 4
        for (int m = lane; m < 512; m += 32) {
            float4 qq = q4[m];
            float4 kk = k4[m];
            s += qq.x * kk.x + qq.y * kk.y + qq.z * kk.z + qq.w * kk.w;
        }
        #pragma unroll
        for (int off = 16; off; off >>= 1) s += __shfl_down_sync(0xFFFFFFFFu, s, off);
        if (lane == 0) s_att[p] = s;
    }
    __syncthreads();

    // 4. scores = attention/sqrt(H) + spatial + edge_bias; masked -> -1e9 exactly
    if (t < Bn * En) {
        int e = t & 15;
        float sc;
        if (mask[e] != 0) {
            float sb = spatial[abs(e - cur)];
            sc = s_att[t] * (1.0f / 45.254833995939045f) + sb + s_eb[e];
        } else {
            sc = -1e9f;
        }
        s_att[t] = sc;
    }
    __syncthreads();

    // 5. softmax per batch (tiny: E=16, serial per thread)
    if (t < Bn) {
        float mx = -3.4e38f;
        #pragma unroll
        for (int e = 0; e < En; e++) mx = fmaxf(mx, s_att[t * En + e]);
        float ex[En];
        float z = 0.f;
        #pragma unroll
        for (int e = 0; e < En; e++) { ex[e] = expf(s_att[t * En + e] - mx); z += ex[e]; }
        float iz = 1.0f / z;
        #pragma unroll
        for (int e = 0; e < En; e++) s_probs[t][e] = ex[e] * iz;
    }
    __syncthreads();

    // 6. loss, argmax, writes
    if (t == 0) {
        int na = 0;
        #pragma unroll
        for (int i = 0; i < En; i++) na += (mask[i] != 0) ? 1 : 0;
        float tp = 1.0f / (float)na;
        float lt = logf(tp);
        float kl = 0.f;
        for (int b = 0; b < Bn; b++)
            for (int e = 0; e < En; e++) {
                float p = fmaxf(s_probs[b][e], 1e-10f);
                kl += tp * (lt - logf(p));
            }
        float loss = (kl / (float)Bn) * 0.01f;

        int am = 0;
        float bm = s_probs[0][0];
        #pragma unroll
        for (int e = 1; e < En; e++) {
            if (s_probs[0][e] > bm) { bm = s_probs[0][e]; am = e; }
        }

        if (out_size != Bn * En) out[0] = loss;            // loss first unless probs-only
        if (out_size >= Bn * En + 2) out[out_size - 1] = (float)am;
    }
    __syncthreads();
    if (t < Bn * En) {
        int b = t >> 4, e = t & 15;
        float p = s_probs[b][e];
        if (out_size == Bn * En)      out[t] = p;
        else if (out_size >= Bn * En + 1) out[1 + t] = p;
    }
}

// ---------------------------------------------------------------------------
// Launcher (graph-capturable: launches only)
// ---------------------------------------------------------------------------
extern "C" void kernel_launch(void* const* d_in, const int* in_sizes, int n_in,
                              void* d_out, int out_size) {
    const float* hidden   = (const float*)d_in[0];
    const float* lemb     = (const float*)d_in[1];
    const float* cemb     = (const float*)d_in[2];
    const float* spatial  = (const float*)d_in[3];
    const float* edge     = (const float*)d_in[4];
    const float* gamma    = (const float*)d_in[5];
    const float* beta     = (const float*)d_in[6];
    const float* Wq       = (const float*)d_in[7];
    const float* bq       = (const float*)d_in[8];
    const float* Wk       = (const float*)d_in[9];
    const float* bk       = (const float*)d_in[10];
    // d_in[11], d_in[12] = Wv, bv : dead code in the reference, skipped.
    const int* curp       = (const int*)d_in[13];
    const int* maskp      = (const int*)d_in[14];
    float* out            = (float*)d_out;

    float* gq_ptr; float* gk_ptr; float* gquery_ptr; float* gfeat_ptr;
    cudaGetSymbolAddress((void**)&gq_ptr, g_q);
    cudaGetSymbolAddress((void**)&gk_ptr, g_k);
    cudaGetSymbolAddress((void**)&gquery_ptr, g_query);
    cudaGetSymbolAddress((void**)&gfeat_ptr, g_features);

    ln_mean_kernel<<<NPART, 256>>>(hidden);
    prep_kernel<<<(Bn * Hn + En * Hn + 255) / 256, 256>>>(lemb, cemb, gamma, beta, curp);
    qk_kernel<En><<<Hn / 16, 256>>>(gfeat_ptr, Wk, bk, gk_ptr);
    qk_kernel<Bn><<<Hn / 16, 256>>>(gquery_ptr, Wq, bq, gq_ptr);
    final_kernel<<<1, 512>>>(spatial, edge, curp, maskp, out, out_size);
}

// round 5
// speedup vs baseline: 1.0121x; 1.0121x over previous
#include <cuda_runtime.h>
#include <cuda_bf16.h>
#include <math.h>

// Problem constants
#define Bn 4
#define Sn 4096
#define Hn 2048
#define En 16
#define EDn 512
#define ROWS_PER_BLOCK 32
#define CHUNKS 128            // chunks per batch
#define NPART (Bn * CHUNKS)   // 512 partial rows

// Scratch (allocation-free: __device__ globals)
__device__ float g_partials[NPART][Hn];   // 4 MB
__device__ float g_query[Bn][Hn];
__device__ float g_features[En][Hn];
__device__ float g_q[Bn][Hn];
__device__ float g_k[En][Hn];

// ---------------------------------------------------------------------------
// Kernel 1: fused LayerNorm + partial mean over S.
// Each block: one batch b, 32 consecutive rows of S. Accumulates
// sum_s (x - mu_s) * rsqrt(var_s + eps) per h into a partial row.
// gamma/beta applied later (they factor out of the mean over S).
// ---------------------------------------------------------------------------
__global__ __launch_bounds__(256) void ln_mean_kernel(const float* __restrict__ hidden) {
    const int bid = blockIdx.x;
    const int b = bid / CHUNKS;
    const int chunk = bid % CHUNKS;
    const int t = threadIdx.x;
    const int lane = t & 31;
    const int wid = t >> 5;

    const float* base = hidden + ((size_t)b * Sn + (size_t)chunk * ROWS_PER_BLOCK) * Hn;

    float4 acc0 = make_float4(0.f, 0.f, 0.f, 0.f);
    float4 acc1 = make_float4(0.f, 0.f, 0.f, 0.f);

    __shared__ float s_red[8][4];
    __shared__ float s_fin[4];

    for (int r = 0; r < ROWS_PER_BLOCK; r += 2) {
        const float4* row0 = (const float4*)(base + (size_t)r * Hn);
        const float4* row1 = (const float4*)(base + (size_t)(r + 1) * Hn);
        float4 a0 = row0[t];
        float4 a1 = row0[t + 256];
        float4 b0 = row1[t];
        float4 b1 = row1[t + 256];

        float s0 = a0.x + a0.y + a0.z + a0.w + a1.x + a1.y + a1.z + a1.w;
        float q0 = a0.x * a0.x + a0.y * a0.y + a0.z * a0.z + a0.w * a0.w
                 + a1.x * a1.x + a1.y * a1.y + a1.z * a1.z + a1.w * a1.w;
        float s1 = b0.x + b0.y + b0.z + b0.w + b1.x + b1.y + b1.z + b1.w;
        float q1 = b0.x * b0.x + b0.y * b0.y + b0.z * b0.z + b0.w * b0.w
                 + b1.x * b1.x + b1.y * b1.y + b1.z * b1.z + b1.w * b1.w;

        #pragma unroll
        for (int off = 16; off; off >>= 1) {
            s0 += __shfl_down_sync(0xFFFFFFFFu, s0, off);
            q0 += __shfl_down_sync(0xFFFFFFFFu, q0, off);
            s1 += __shfl_down_sync(0xFFFFFFFFu, s1, off);
            q1 += __shfl_down_sync(0xFFFFFFFFu, q1, off);
        }
        if (lane == 0) {
            s_red[wid][0] = s0; s_red[wid][1] = q0;
            s_red[wid][2] = s1; s_red[wid][3] = q1;
        }
        __syncthreads();
        if (wid == 0) {
            float v0 = (lane < 8) ? s_red[lane][0] : 0.f;
            float v1 = (lane < 8) ? s_red[lane][1] : 0.f;
            float v2 = (lane < 8) ? s_red[lane][2] : 0.f;
            float v3 = (lane < 8) ? s_red[lane][3] : 0.f;
            #pragma unroll
            for (int off = 4; off; off >>= 1) {
                v0 += __shfl_down_sync(0xFFFFFFFFu, v0, off);
                v1 += __shfl_down_sync(0xFFFFFFFFu, v1, off);
                v2 += __shfl_down_sync(0xFFFFFFFFu, v2, off);
                v3 += __shfl_down_sync(0xFFFFFFFFu, v3, off);
            }
            if (lane == 0) {
                s_fin[0] = v0; s_fin[1] = v1; s_fin[2] = v2; s_fin[3] = v3;
            }
        }
        __syncthreads();
        const float inv = 1.0f / (float)Hn;
        float mu0 = s_fin[0] * inv;
        float rs0 = rsqrtf(s_fin[1] * inv - mu0 * mu0 + 1e-5f);
        float mu1 = s_fin[2] * inv;
        float rs1 = rsqrtf(s_fin[3] * inv - mu1 * mu1 + 1e-5f);

        acc0.x += (a0.x - mu0) * rs0 + (b0.x - mu1) * rs1;
        acc0.y += (a0.y - mu0) * rs0 + (b0.y - mu1) * rs1;
        acc0.z += (a0.z - mu0) * rs0 + (b0.z - mu1) * rs1;
        acc0.w += (a0.w - mu0) * rs0 + (b0.w - mu1) * rs1;
        acc1.x += (a1.x - mu0) * rs0 + (b1.x - mu1) * rs1;
        acc1.y += (a1.y - mu0) * rs0 + (b1.y - mu1) * rs1;
        acc1.z += (a1.z - mu0) * rs0 + (b1.z - mu1) * rs1;
        acc1.w += (a1.w - mu0) * rs0 + (b1.w - mu1) * rs1;
    }

    float4* p = (float4*)(&g_partials[bid][0]);
    p[t] = acc0;
    p[t + 256] = acc1;
}

// ---------------------------------------------------------------------------
// Kernel 2: reduce partials -> query_input; build features = lemb + cemb.
// ---------------------------------------------------------------------------
__global__ __launch_bounds__(256) void prep_kernel(const float* __restrict__ lemb,
                                                   const float* __restrict__ cemb,
                                                   const float* __restrict__ gamma,
                                                   const float* __restrict__ beta,
                                                   const int* __restrict__ curp) {
    int idx = blockIdx.x * blockDim.x + threadIdx.x;
    int cur = *curp;
    if (idx < Bn * Hn) {
        int b = idx / Hn, h = idx % Hn;
        float s = 0.f;
        #pragma unroll 4
        for (int p = 0; p < CHUNKS; p++) s += g_partials[b * CHUNKS + p][h];
        float hm = s * (1.0f / (float)Sn) * gamma[h] + beta[h];
        g_query[b][h] = lemb[cur * Hn + h] + hm;
    } else {
        int idx2 = idx - Bn * Hn;
        if (idx2 < En * Hn) {
            (&g_features[0][0])[idx2] = lemb[idx2] + cemb[idx2];
        }
    }
}

// ---------------------------------------------------------------------------
// Kernel 3: skinny GEMM  out[N][H] = L[N][H] @ W^T + bias.
// Warp computes 2 output columns h; lanes split the K dimension (float4).
// ---------------------------------------------------------------------------
template <int N>
__global__ __launch_bounds__(256) void qk_kernel(const float* __restrict__ L,
                                                 const float* __restrict__ W,
                                                 const float* __restrict__ bias,
                                                 float* __restrict__ out) {
    const int t = threadIdx.x;
    const int lane = t & 31;
    const int w = t >> 5;
    const int h0 = blockIdx.x * 16 + w * 2;

    const float4* W4 = (const float4*)W;
    const float4* L4 = (const float4*)L;

    float acc0[N], acc1[N];
    #pragma unroll
    for (int e = 0; e < N; e++) { acc0[e] = 0.f; acc1[e] = 0.f; }

    for (int j = 0; j < 16; j++) {
        int c4 = lane + 32 * j;  // float4 index within a 2048-float row
        float4 w0 = W4[(size_t)h0 * 512 + c4];
        float4 w1 = W4[(size_t)(h0 + 1) * 512 + c4];
        #pragma unroll
        for (int e = 0; e < N; e++) {
            float4 l = L4[e * 512 + c4];
            acc0[e] += w0.x * l.x + w0.y * l.y + w0.z * l.z + w0.w * l.w;
            acc1[e] += w1.x * l.x + w1.y * l.y + w1.z * l.z + w1.w * l.w;
        }
    }

    #pragma unroll
    for (int e = 0; e < N; e++) {
        #pragma unroll
        for (int off = 16; off; off >>= 1) {
            acc0[e] += __shfl_down_sync(0xFFFFFFFFu, acc0[e], off);
            acc1[e] += __shfl_down_sync(0xFFFFFFFFu, acc1[e], off);
        }
    }
    if (lane == 0) {
        float b0 = bias[h0], b1 = bias[h0 + 1];
        #pragma unroll
        for (int e = 0; e < N; e++) {
            out[e * Hn + h0]     = acc0[e] + b0;
            out[e * Hn + h0 + 1] = acc1[e] + b1;
        }
    }
}

// ---------------------------------------------------------------------------
// Kernel 4: scores, biases, softmax, KL loss, argmax. Single block.
// ---------------------------------------------------------------------------
__global__ __launch_bounds__(512) void final_kernel(const float* __restrict__ spatial,
                                                    const float* __restrict__ edge,
                                                    const int* __restrict__ curp,
                                                    const int* __restrict__ mask,
                                                    float* __restrict__ out,
                                                    int out_size) {
    __shared__ float s_u[EDn];
    __shared__ float s_eb[En];
    __shared__ float s_att[Bn * En];
    __shared__ float s_probs[Bn][En];

    const int t = threadIdx.x;
    const int lane = t & 31;
    const int w = t >> 5;
    const int cur = *curp;

    // 1. u[d] = sum_i coef_i * edge[i][d]
    if (t < EDn) {
        float u = 0.f;
        #pragma unroll
        for (int i = 0; i < En; i++) {
            int d = abs(i - cur);
            float coef = (mask[i] != 0 && i != cur) ? 1.0f / (float)max(d, 1) : 0.0f;
            u += coef * edge[i * EDn + t];
        }
        s_u[t] = u;
    }
    __syncthreads();

    // 2. edge_bias[j] = dot(u, edge[j]) : one warp per j
    {
        float s = 0.f;
        const float* ej = edge + w * EDn;
        for (int d = lane; d < EDn; d += 32) s += s_u[d] * ej[d];
        #pragma unroll
        for (int off = 16; off; off >>= 1) s += __shfl_down_sync(0xFFFFFFFFu, s, off);
        if (lane == 0) s_eb[w] = s;
    }

    // 3. attention[b][e] = dot(q[b], k[e]); warp w handles 4 pairs
    for (int r = 0; r < 4; r++) {
        int p = w * 4 + r;
        int b = p >> 4;
        int e = p & 15;
        const float4* q4 = (const float4*)(&g_q[b][0]);
        const float4* k4 = (const float4*)(&g_k[e][0]);
        float s = 0.f;
        #pragma unroll 4
        for (int m = lane; m < 512; m += 32) {
            float4 qq = q4[m];
            float4 kk = k4[m];
            s += qq.x * kk.x + qq.y * kk.y + qq.z * kk.z + qq.w * kk.w;
        }
        #pragma unroll
        for (int off = 16; off; off >>= 1) s += __shfl_down_sync(0xFFFFFFFFu, s, off);
        if (lane == 0) s_att[p] = s;
    }
    __syncthreads();

    // 4. scores = attention/sqrt(H) + spatial + edge_bias; masked -> -1e9 exactly
    if (t < Bn * En) {
        int e = t & 15;
        float sc;
        if (mask[e] != 0) {
            float sb = spatial[abs(e - cur)];
            sc = s_att[t] * (1.0f / 45.254833995939045f) + sb + s_eb[e];
        } else {
            sc = -1e9f;
        }
        s_att[t] = sc;
    }
    __syncthreads();

    // 5. softmax per batch (tiny: E=16, serial per thread)
    if (t < Bn) {
        float mx = -3.4e38f;
        #pragma unroll
        for (int e = 0; e < En; e++) mx = fmaxf(mx, s_att[t * En + e]);
        float ex[En];
        float z = 0.f;
        #pragma unroll
        for (int e = 0; e < En; e++) { ex[e] = expf(s_att[t * En + e] - mx); z += ex[e]; }
        float iz = 1.0f / z;
        #pragma unroll
        for (int e = 0; e < En; e++) s_probs[t][e] = ex[e] * iz;
    }
    __syncthreads();

    // 6. loss, argmax, writes
    if (t == 0) {
        int na = 0;
        #pragma unroll
        for (int i = 0; i < En; i++) na += (mask[i] != 0) ? 1 : 0;
        float tp = 1.0f / (float)na;
        float lt = logf(tp);
        float kl = 0.f;
        for (int b = 0; b < Bn; b++)
            for (int e = 0; e < En; e++) {
                float p = fmaxf(s_probs[b][e], 1e-10f);
                kl += tp * (lt - logf(p));
            }
        float loss = (kl / (float)Bn) * 0.01f;

        int am = 0;
        float bm = s_probs[0][0];
        #pragma unroll
        for (int e = 1; e < En; e++) {
            if (s_probs[0][e] > bm) { bm = s_probs[0][e]; am = e; }
        }

        if (out_size != Bn * En) out[0] = loss;            // loss first unless probs-only
        if (out_size >= Bn * En + 2) out[out_size - 1] = (float)am;
    }
    __syncthreads();
    if (t < Bn * En) {
        int b = t >> 4, e = t & 15;
        float p = s_probs[b][e];
        if (out_size == Bn * En)      out[t] = p;
        else if (out_size >= Bn * En + 1) out[1 + t] = p;
    }
}

// ---------------------------------------------------------------------------
// Launcher (graph-capturable: launches only)
// ---------------------------------------------------------------------------
extern "C" void kernel_launch(void* const* d_in, const int* in_sizes, int n_in,
                              void* d_out, int out_size) {
    const float* hidden   = (const float*)d_in[0];
    const float* lemb     = (const float*)d_in[1];
    const float* cemb     = (const float*)d_in[2];
    const float* spatial  = (const float*)d_in[3];
    const float* edge     = (const float*)d_in[4];
    const float* gamma    = (const float*)d_in[5];
    const float* beta     = (const float*)d_in[6];
    const float* Wq       = (const float*)d_in[7];
    const float* bq       = (const float*)d_in[8];
    const float* Wk       = (const float*)d_in[9];
    const float* bk       = (const float*)d_in[10];
    // d_in[11], d_in[12] = Wv, bv : dead code in the reference, skipped.
    const int* curp       = (const int*)d_in[13];
    const int* maskp      = (const int*)d_in[14];
    float* out            = (float*)d_out;

    float* gq_ptr; float* gk_ptr; float* gquery_ptr; float* gfeat_ptr;
    cudaGetSymbolAddress((void**)&gq_ptr, g_q);
    cudaGetSymbolAddress((void**)&gk_ptr, g_k);
    cudaGetSymbolAddress((void**)&gquery_ptr, g_query);
    cudaGetSymbolAddress((void**)&gfeat_ptr, g_features);

    ln_mean_kernel<<<NPART, 256>>>(hidden);
    prep_kernel<<<(Bn * Hn + En * Hn + 255) / 256, 256>>>(lemb, cemb, gamma, beta, curp);
    qk_kernel<En><<<Hn / 16, 256>>>(gfeat_ptr, Wk, bk, gk_ptr);
    qk_kernel<Bn><<<Hn / 16, 256>>>(gquery_ptr, Wq, bq, gq_ptr);
    final_kernel<<<1, 512>>>(spatial, edge, curp, maskp, out, out_size);
}

// round 6
// speedup vs baseline: 1.0196x; 1.0074x over previous
#include <cuda_runtime.h>
#include <cuda_bf16.h>
#include <math.h>

// Problem constants
#define Bn 4
#define Sn 4096
#define Hn 2048
#define En 16
#define EDn 512
#define ROWS_PER_BLOCK 32
#define CHUNKS 128            // chunks per batch
#define NPART (Bn * CHUNKS)   // 512 partial rows

// Scratch (allocation-free: __device__ globals)
__device__ float g_partials[NPART][Hn];   // 4 MB
__device__ float g_query[Bn][Hn];
__device__ float g_features[En][Hn];
__device__ float g_q[Bn][Hn];
__device__ float g_k[En][Hn];

// ---------------------------------------------------------------------------
// Kernel 1: fused LayerNorm + partial mean over S.
// Each block: one batch b, 32 consecutive rows of S. Accumulates
// sum_s (x - mu_s) * rsqrt(var_s + eps) per h into a partial row.
// gamma/beta applied later (they factor out of the mean over S).
// ---------------------------------------------------------------------------
__global__ __launch_bounds__(256) void ln_mean_kernel(const float* __restrict__ hidden) {
    const int bid = blockIdx.x;
    const int b = bid / CHUNKS;
    const int chunk = bid % CHUNKS;
    const int t = threadIdx.x;
    const int lane = t & 31;
    const int wid = t >> 5;

    const float* base = hidden + ((size_t)b * Sn + (size_t)chunk * ROWS_PER_BLOCK) * Hn;

    float4 acc0 = make_float4(0.f, 0.f, 0.f, 0.f);
    float4 acc1 = make_float4(0.f, 0.f, 0.f, 0.f);

    __shared__ float s_red[8][4];
    __shared__ float s_fin[4];

    for (int r = 0; r < ROWS_PER_BLOCK; r += 2) {
        const float4* row0 = (const float4*)(base + (size_t)r * Hn);
        const float4* row1 = (const float4*)(base + (size_t)(r + 1) * Hn);
        float4 a0 = row0[t];
        float4 a1 = row0[t + 256];
        float4 b0 = row1[t];
        float4 b1 = row1[t + 256];

        float s0 = a0.x + a0.y + a0.z + a0.w + a1.x + a1.y + a1.z + a1.w;
        float q0 = a0.x * a0.x + a0.y * a0.y + a0.z * a0.z + a0.w * a0.w
                 + a1.x * a1.x + a1.y * a1.y + a1.z * a1.z + a1.w * a1.w;
        float s1 = b0.x + b0.y + b0.z + b0.w + b1.x + b1.y + b1.z + b1.w;
        float q1 = b0.x * b0.x + b0.y * b0.y + b0.z * b0.z + b0.w * b0.w
                 + b1.x * b1.x + b1.y * b1.y + b1.z * b1.z + b1.w * b1.w;

        #pragma unroll
        for (int off = 16; off; off >>= 1) {
            s0 += __shfl_down_sync(0xFFFFFFFFu, s0, off);
            q0 += __shfl_down_sync(0xFFFFFFFFu, q0, off);
            s1 += __shfl_down_sync(0xFFFFFFFFu, s1, off);
            q1 += __shfl_down_sync(0xFFFFFFFFu, q1, off);
        }
        if (lane == 0) {
            s_red[wid][0] = s0; s_red[wid][1] = q0;
            s_red[wid][2] = s1; s_red[wid][3] = q1;
        }
        __syncthreads();
        if (wid == 0) {
            float v0 = (lane < 8) ? s_red[lane][0] : 0.f;
            float v1 = (lane < 8) ? s_red[lane][1] : 0.f;
            float v2 = (lane < 8) ? s_red[lane][2] : 0.f;
            float v3 = (lane < 8) ? s_red[lane][3] : 0.f;
            #pragma unroll
            for (int off = 4; off; off >>= 1) {
                v0 += __shfl_down_sync(0xFFFFFFFFu, v0, off);
                v1 += __shfl_down_sync(0xFFFFFFFFu, v1, off);
                v2 += __shfl_down_sync(0xFFFFFFFFu, v2, off);
                v3 += __shfl_down_sync(0xFFFFFFFFu, v3, off);
            }
            if (lane == 0) {
                s_fin[0] = v0; s_fin[1] = v1; s_fin[2] = v2; s_fin[3] = v3;
            }
        }
        __syncthreads();
        const float inv = 1.0f / (float)Hn;
        float mu0 = s_fin[0] * inv;
        float rs0 = rsqrtf(s_fin[1] * inv - mu0 * mu0 + 1e-5f);
        float mu1 = s_fin[2] * inv;
        float rs1 = rsqrtf(s_fin[3] * inv - mu1 * mu1 + 1e-5f);

        acc0.x += (a0.x - mu0) * rs0 + (b0.x - mu1) * rs1;
        acc0.y += (a0.y - mu0) * rs0 + (b0.y - mu1) * rs1;
        acc0.z += (a0.z - mu0) * rs0 + (b0.z - mu1) * rs1;
        acc0.w += (a0.w - mu0) * rs0 + (b0.w - mu1) * rs1;
        acc1.x += (a1.x - mu0) * rs0 + (b1.x - mu1) * rs1;
        acc1.y += (a1.y - mu0) * rs0 + (b1.y - mu1) * rs1;
        acc1.z += (a1.z - mu0) * rs0 + (b1.z - mu1) * rs1;
        acc1.w += (a1.w - mu0) * rs0 + (b1.w - mu1) * rs1;
    }

    float4* p = (float4*)(&g_partials[bid][0]);
    p[t] = acc0;
    p[t + 256] = acc1;
}

// ---------------------------------------------------------------------------
// Kernel 2: reduce partials -> query_input; build features = lemb + cemb.
// ---------------------------------------------------------------------------
__global__ __launch_bounds__(256) void prep_kernel(const float* __restrict__ lemb,
                                                   const float* __restrict__ cemb,
                                                   const float* __restrict__ gamma,
                                                   const float* __restrict__ beta,
                                                   const int* __restrict__ curp) {
    int idx = blockIdx.x * blockDim.x + threadIdx.x;
    int cur = *curp;
    if (idx < Bn * Hn) {
        int b = idx / Hn, h = idx % Hn;
        float s = 0.f;
        #pragma unroll 4
        for (int p = 0; p < CHUNKS; p++) s += g_partials[b * CHUNKS + p][h];
        float hm = s * (1.0f / (float)Sn) * gamma[h] + beta[h];
        g_query[b][h] = lemb[cur * Hn + h] + hm;
    } else {
        int idx2 = idx - Bn * Hn;
        if (idx2 < En * Hn) {
            (&g_features[0][0])[idx2] = lemb[idx2] + cemb[idx2];
        }
    }
}

// ---------------------------------------------------------------------------
// Kernel 3: skinny GEMM  out[N][H] = L[N][H] @ W^T + bias.
// Warp computes 2 output columns h; lanes split the K dimension (float4).
// ---------------------------------------------------------------------------
template <int N>
__global__ __launch_bounds__(256) void qk_kernel(const float* __restrict__ L,
                                                 const float* __restrict__ W,
                                                 const float* __restrict__ bias,
                                                 float* __restrict__ out) {
    const int t = threadIdx.x;
    const int lane = t & 31;
    const int w = t >> 5;
    const int h0 = blockIdx.x * 16 + w * 2;

    const float4* W4 = (const float4*)W;
    const float4* L4 = (const float4*)L;

    float acc0[N], acc1[N];
    #pragma unroll
    for (int e = 0; e < N; e++) { acc0[e] = 0.f; acc1[e] = 0.f; }

    for (int j = 0; j < 16; j++) {
        int c4 = lane + 32 * j;  // float4 index within a 2048-float row
        float4 w0 = W4[(size_t)h0 * 512 + c4];
        float4 w1 = W4[(size_t)(h0 + 1) * 512 + c4];
        #pragma unroll
        for (int e = 0; e < N; e++) {
            float4 l = L4[e * 512 + c4];
            acc0[e] += w0.x * l.x + w0.y * l.y + w0.z * l.z + w0.w * l.w;
            acc1[e] += w1.x * l.x + w1.y * l.y + w1.z * l.z + w1.w * l.w;
        }
    }

    #pragma unroll
    for (int e = 0; e < N; e++) {
        #pragma unroll
        for (int off = 16; off; off >>= 1) {
            acc0[e] += __shfl_down_sync(0xFFFFFFFFu, acc0[e], off);
            acc1[e] += __shfl_down_sync(0xFFFFFFFFu, acc1[e], off);
        }
    }
    if (lane == 0) {
        float b0 = bias[h0], b1 = bias[h0 + 1];
        #pragma unroll
        for (int e = 0; e < N; e++) {
            out[e * Hn + h0]     = acc0[e] + b0;
            out[e * Hn + h0 + 1] = acc1[e] + b1;
        }
    }
}

// ---------------------------------------------------------------------------
// Kernel 4: scores, biases, softmax, KL loss, argmax. Single block.
// ---------------------------------------------------------------------------
__global__ __launch_bounds__(512) void final_kernel(const float* __restrict__ spatial,
                                                    const float* __restrict__ edge,
                                                    const int* __restrict__ curp,
                                                    const int* __restrict__ mask,
                                                    float* __restrict__ out,
                                                    int out_size) {
    __shared__ float s_u[EDn];
    __shared__ float s_eb[En];
    __shared__ float s_att[Bn * En];
    __shared__ float s_probs[Bn][En];

    const int t = threadIdx.x;
    const int lane = t & 31;
    const int w = t >> 5;
    const int cur = *curp;

    // 1. u[d] = sum_i coef_i * edge[i][d]
    if (t < EDn) {
        float u = 0.f;
        #pragma unroll
        for (int i = 0; i < En; i++) {
            int d = abs(i - cur);
            float coef = (mask[i] != 0 && i != cur) ? 1.0f / (float)max(d, 1) : 0.0f;
            u += coef * edge[i * EDn + t];
        }
        s_u[t] = u;
    }
    __syncthreads();

    // 2. edge_bias[j] = dot(u, edge[j]) : one warp per j
    {
        float s = 0.f;
        const float* ej = edge + w * EDn;
        for (int d = lane; d < EDn; d += 32) s += s_u[d] * ej[d];
        #pragma unroll
        for (int off = 16; off; off >>= 1) s += __shfl_down_sync(0xFFFFFFFFu, s, off);
        if (lane == 0) s_eb[w] = s;
    }

    // 3. attention[b][e] = dot(q[b], k[e]); warp w handles 4 pairs
    for (int r = 0; r < 4; r++) {
        int p = w * 4 + r;
        int b = p >> 4;
        int e = p & 15;
        const float4* q4 = (const float4*)(&g_q[b][0]);
        const float4* k4 = (const float4*)(&g_k[e][0]);
        float s = 0.f;
        #pragma unroll 4
        for (int m = lane; m < 512; m += 32) {
            float4 qq = q4[m];
            float4 kk = k4[m];
            s += qq.x * kk.x + qq.y * kk.y + qq.z * kk.z + qq.w * kk.w;
        }
        #pragma unroll
        for (int off = 16; off; off >>= 1) s += __shfl_down_sync(0xFFFFFFFFu, s, off);
        if (lane == 0) s_att[p] = s;
    }
    __syncthreads();

    // 4. scores = attention/sqrt(H) + spatial + edge_bias; masked -> -1e9 exactly
    if (t < Bn * En) {
        int e = t & 15;
        float sc;
        if (mask[e] != 0) {
            float sb = spatial[abs(e - cur)];
            sc = s_att[t] * (1.0f / 45.254833995939045f) + sb + s_eb[e];
        } else {
            sc = -1e9f;
        }
        s_att[t] = sc;
    }
    __syncthreads();

    // 5. softmax per batch (tiny: E=16, serial per thread)
    if (t < Bn) {
        float mx = -3.4e38f;
        #pragma unroll
        for (int e = 0; e < En; e++) mx = fmaxf(mx, s_att[t * En + e]);
        float ex[En];
        float z = 0.f;
        #pragma unroll
        for (int e = 0; e < En; e++) { ex[e] = expf(s_att[t * En + e] - mx); z += ex[e]; }
        float iz = 1.0f / z;
        #pragma unroll
        for (int e = 0; e < En; e++) s_probs[t][e] = ex[e] * iz;
    }
    __syncthreads();

    // 6. loss, argmax, writes
    if (t == 0) {
        int na = 0;
        #pragma unroll
        for (int i = 0; i < En; i++) na += (mask[i] != 0) ? 1 : 0;
        float tp = 1.0f / (float)na;
        float lt = logf(tp);
        float kl = 0.f;
        for (int b = 0; b < Bn; b++)
            for (int e = 0; e < En; e++) {
                float p = fmaxf(s_probs[b][e], 1e-10f);
                kl += tp * (lt - logf(p));
            }
        float loss = (kl / (float)Bn) * 0.01f;

        int am = 0;
        float bm = s_probs[0][0];
        #pragma unroll
        for (int e = 1; e < En; e++) {
            if (s_probs[0][e] > bm) { bm = s_probs[0][e]; am = e; }
        }

        if (out_size != Bn * En) out[0] = loss;            // loss first unless probs-only
        if (out_size >= Bn * En + 2) out[out_size - 1] = (float)am;
    }
    __syncthreads();
    if (t < Bn * En) {
        int b = t >> 4, e = t & 15;
        float p = s_probs[b][e];
        if (out_size == Bn * En)      out[t] = p;
        else if (out_size >= Bn * En + 1) out[1 + t] = p;
    }
}

// ---------------------------------------------------------------------------
// Launcher (graph-capturable: launches only)
// ---------------------------------------------------------------------------
extern "C" void kernel_launch(void* const* d_in, const int* in_sizes, int n_in,
                              void* d_out, int out_size) {
    const float* hidden   = (const float*)d_in[0];
    const float* lemb     = (const float*)d_in[1];
    const float* cemb     = (const float*)d_in[2];
    const float* spatial  = (const float*)d_in[3];
    const float* edge     = (const float*)d_in[4];
    const float* gamma    = (const float*)d_in[5];
    const float* beta     = (const float*)d_in[6];
    const float* Wq       = (const float*)d_in[7];
    const float* bq       = (const float*)d_in[8];
    const float* Wk       = (const float*)d_in[9];
    const float* bk       = (const float*)d_in[10];
    // d_in[11], d_in[12] = Wv, bv : dead code in the reference, skipped.
    const int* curp       = (const int*)d_in[13];
    const int* maskp      = (const int*)d_in[14];
    float* out            = (float*)d_out;

    float* gq_ptr; float* gk_ptr; float* gquery_ptr; float* gfeat_ptr;
    cudaGetSymbolAddress((void**)&gq_ptr, g_q);
    cudaGetSymbolAddress((void**)&gk_ptr, g_k);
    cudaGetSymbolAddress((void**)&gquery_ptr, g_query);
    cudaGetSymbolAddress((void**)&gfeat_ptr, g_features);

    ln_mean_kernel<<<NPART, 256>>>(hidden);
    prep_kernel<<<(Bn * Hn + En * Hn + 255) / 256, 256>>>(lemb, cemb, gamma, beta, curp);
    qk_kernel<En><<<Hn / 16, 256>>>(gfeat_ptr, Wk, bk, gk_ptr);
    qk_kernel<Bn><<<Hn / 16, 256>>>(gquery_ptr, Wq, bq, gq_ptr);
    final_kernel<<<1, 512>>>(spatial, edge, curp, maskp, out, out_size);
}